// round 11
// baseline (speedup 1.0000x reference)
#include <cuda_runtime.h>
#include <cuda_bf16.h>
#include <cstdint>

#define M_TOK   16384
#define D_DIM   1024
#define H_DIM   4096

// ---------------- scratch (static device memory; no allocations) -----------
__device__ __align__(16) __nv_bfloat16 g_xb [M_TOK * D_DIM];
__device__ __align__(16) __nv_bfloat16 g_w1b[H_DIM * D_DIM];
__device__ __align__(16) __nv_bfloat16 g_w2b[D_DIM * H_DIM];
__device__ __align__(16) float         g_h  [(size_t)M_TOK * H_DIM];
__device__ __align__(16) __nv_bfloat16 g_hb [(size_t)M_TOK * H_DIM];
__device__ unsigned g_amax[4];      // 0: x, 1: w1, 2: w2, 3: h (fp32 bits)

// ---------------- helpers ---------------------------------------------------
__device__ __forceinline__ unsigned smem_u32(const void* p) {
    return (unsigned)__cvta_generic_to_shared(p);
}
__device__ __forceinline__ void cp16(unsigned dst, const void* src) {
    asm volatile("cp.async.cg.shared.global [%0], [%1], 16;\n" :: "r"(dst), "l"(src));
}
__device__ __forceinline__ void cp_commit() {
    asm volatile("cp.async.commit_group;\n");
}
template <int N>
__device__ __forceinline__ void cp_wait() {
    asm volatile("cp.async.wait_group %0;\n" :: "n"(N));
}
__device__ __forceinline__ void ldsm4(unsigned& r0, unsigned& r1, unsigned& r2,
                                      unsigned& r3, unsigned addr) {
    asm volatile("ldmatrix.sync.aligned.m8n8.x4.shared.b16 {%0,%1,%2,%3}, [%4];"
                 : "=r"(r0), "=r"(r1), "=r"(r2), "=r"(r3) : "r"(addr));
}

#define MMA_BF16(d, a, b)                                                      \
    asm volatile(                                                              \
        "mma.sync.aligned.m16n8k16.row.col.f32.bf16.bf16.f32 "                 \
        "{%0,%1,%2,%3},{%4,%5,%6,%7},{%8,%9},{%0,%1,%2,%3};"                   \
        : "+f"(d[0]), "+f"(d[1]), "+f"(d[2]), "+f"(d[3])                       \
        : "r"(a[0]), "r"(a[1]), "r"(a[2]), "r"(a[3]), "r"(b[0]), "r"(b[1]))

// ---------------- fused prep kernels ----------------------------------------
__global__ void init_kernel() {
    if (threadIdx.x < 4) g_amax[threadIdx.x] = 0u;
}

// blocks [0,1024): x | [1024,1280): w1 | [1280,1536): w2
__global__ void absmax_all_kernel(const float4* __restrict__ x,
                                  const float4* __restrict__ w1,
                                  const float4* __restrict__ w2) {
    const float4* p;
    int n4, slot, lb, nb;
    int b = blockIdx.x;
    if (b < 1024)      { p = x;  n4 = (M_TOK * D_DIM) / 4; slot = 0; lb = b;        nb = 1024; }
    else if (b < 1280) { p = w1; n4 = (H_DIM * D_DIM) / 4; slot = 1; lb = b - 1024; nb = 256; }
    else               { p = w2; n4 = (D_DIM * H_DIM) / 4; slot = 2; lb = b - 1280; nb = 256; }

    float m = 0.f;
    for (int i = lb * blockDim.x + threadIdx.x; i < n4; i += nb * blockDim.x) {
        float4 v = p[i];
        m = fmaxf(m, fmaxf(fmaxf(fabsf(v.x), fabsf(v.y)),
                           fmaxf(fabsf(v.z), fabsf(v.w))));
    }
    #pragma unroll
    for (int o = 16; o > 0; o >>= 1)
        m = fmaxf(m, __shfl_xor_sync(0xffffffffu, m, o));
    __shared__ float sm[8];
    if ((threadIdx.x & 31) == 0) sm[threadIdx.x >> 5] = m;
    __syncthreads();
    if (threadIdx.x == 0) {
        float v = sm[0];
        #pragma unroll
        for (int i = 1; i < 8; ++i) v = fmaxf(v, sm[i]);
        atomicMax(&g_amax[slot], __float_as_uint(v));
    }
}

__device__ __forceinline__ float quantf(float v, float scale) {
    return fminf(fmaxf(rintf(v / scale), -127.f), 127.f);
}
__device__ __forceinline__ unsigned short bf16bits(float v) {
    __nv_bfloat16 h = __float2bfloat16(v);
    return *(unsigned short*)&h;
}

// blocks [0,16384): x | [16384,20480): w1 | [20480,24576): w2  (all -> bf16 ints)
__global__ void quant_all_kernel(const float4* __restrict__ x,
                                 const float4* __restrict__ w1,
                                 const float4* __restrict__ w2) {
    int b = blockIdx.x;
    const float4* src;
    ushort4* dst;
    int i, slot;
    if (b < 16384)      { src = x;  dst = (ushort4*)g_xb;  i = b * blockDim.x + threadIdx.x;            slot = 0; }
    else if (b < 20480) { src = w1; dst = (ushort4*)g_w1b; i = (b - 16384) * blockDim.x + threadIdx.x;  slot = 1; }
    else                { src = w2; dst = (ushort4*)g_w2b; i = (b - 20480) * blockDim.x + threadIdx.x;  slot = 2; }
    float scale = fmaxf(__uint_as_float(g_amax[slot]), 1e-8f) / 127.f;
    float4 v = src[i];
    ushort4 o;
    o.x = bf16bits(quantf(v.x, scale));
    o.y = bf16bits(quantf(v.y, scale));
    o.z = bf16bits(quantf(v.z, scale));
    o.w = bf16bits(quantf(v.w, scale));
    dst[i] = o;
}

__global__ void quant_h_kernel(const float4* __restrict__ x,
                               ushort4* __restrict__ q, int n4) {
    float scale = fmaxf(__uint_as_float(g_amax[3]), 1e-8f) / 127.f;
    int i = blockIdx.x * blockDim.x + threadIdx.x;
    if (i < n4) {
        float4 v = x[i];
        ushort4 o;
        o.x = bf16bits(quantf(v.x, scale));
        o.y = bf16bits(quantf(v.y, scale));
        o.z = bf16bits(quantf(v.z, scale));
        o.w = bf16bits(quantf(v.w, scale));
        q[i] = o;
    }
}

// ---------------- bf16 GEMM (8 warps 32x64, dbl-buf frags, 3-stage) ----------
// C[M,N] = A[M,K](bf16 row-major) * B[N,K](bf16 row-major as col-major op)
// Block 128x128, 256 threads (8 warps, 4x2), warp tile 32x64, BK=64 (128B).
// acc = 64 regs/thread -> room to double-buffer ldmatrix fragments so LDSM
// (crossbar) overlaps MMA (tensor) WITHIN each warp.
#define GSTAGE  32768
#define GB_OFF  16384

template <int EPI>
__global__ __launch_bounds__(256, 1)
void gemm_bf16_kernel(const __nv_bfloat16* __restrict__ A,
                      const __nv_bfloat16* __restrict__ B,
                      const float* __restrict__ bias,
                      float* __restrict__ Cout,
                      int K, int N, int saslot, int sbslot) {
    extern __shared__ __align__(128) char smem[];
    const uint32_t sbase = smem_u32(smem);

    const int tid  = threadIdx.x;
    const int lane = tid & 31;
    const int warp = tid >> 5;
    const int wm = (warp >> 1) * 32;   // 4 warp rows of 32
    const int wn = (warp & 1) * 64;    // 2 warp cols of 64

    const int rowA0 = blockIdx.y * 128;
    const int colB0 = blockIdx.x * 128;

    float acc[2][8][4];
    #pragma unroll
    for (int i = 0; i < 2; ++i)
        #pragma unroll
        for (int j = 0; j < 8; ++j)
            #pragma unroll
            for (int r = 0; r < 4; ++r) acc[i][j][r] = 0.f;

    const int KT = K >> 6;
    const size_t Kb = (size_t)K * 2;

    // loader: 256 threads, 4 chunks per matrix per thread
    const int ld_row = tid >> 3;            // 0..31
    const int ld_c16 = (tid & 7) << 4;
    auto load_stage = [&](int st, int kt) {
        const uint32_t stoff = sbase + st * GSTAGE;
        const size_t k0b = (size_t)kt * 128;
        const char* Ab = (const char*)A + (size_t)rowA0 * Kb + k0b + ld_c16;
        const char* Bb = (const char*)B + (size_t)colB0 * Kb + k0b + ld_c16;
        #pragma unroll
        for (int m = 0; m < 4; ++m) {
            const int row = (m << 5) + ld_row;
            const uint32_t sw = (uint32_t)(row * 128 + (ld_c16 ^ ((row & 7) << 4)));
            cp16(stoff + sw,          Ab + (size_t)row * Kb);
            cp16(stoff + GB_OFF + sw, Bb + (size_t)row * Kb);
        }
        cp_commit();
    };

    load_stage(0, 0);
    load_stage(1, 1);

    // ldmatrix lane geometry
    const int a_row = lane & 15;
    const int a_sel = (lane >> 4) << 4;
    const int b_row = (lane & 7) + (((lane >> 3) & 1) << 3);
    const int b_sel = (lane >> 4) << 4;
    const uint32_t a_swx = (uint32_t)((a_row & 7) << 4);
    const uint32_t b_swx = (uint32_t)((b_row & 7) << 4);
    uint32_t acol[4], bcol[4];
    #pragma unroll
    for (int ks = 0; ks < 4; ++ks) {
        acol[ks] = (uint32_t)((ks * 32 + a_sel) ^ a_swx);
        bcol[ks] = (uint32_t)((ks * 32 + b_sel) ^ b_swx);
    }
    const uint32_t aRowOff = (uint32_t)((wm + a_row) * 128);
    const uint32_t bRowOff = (uint32_t)(GB_OFF + (wn + b_row) * 128);

    unsigned afr[2][2][4], bfr[2][8][2];

    #define LOAD_FRAGS(BUFIDX, ABASE, BBASE, KS)                               \
        do {                                                                   \
            _Pragma("unroll")                                                  \
            for (int i = 0; i < 2; ++i)                                        \
                ldsm4(afr[BUFIDX][i][0], afr[BUFIDX][i][1],                    \
                      afr[BUFIDX][i][2], afr[BUFIDX][i][3],                    \
                      (ABASE) + (uint32_t)(i * 16 * 128) + acol[KS]);          \
            _Pragma("unroll")                                                  \
            for (int jg = 0; jg < 4; ++jg)                                     \
                ldsm4(bfr[BUFIDX][2 * jg][0], bfr[BUFIDX][2 * jg + 1][0],      \
                      bfr[BUFIDX][2 * jg][1], bfr[BUFIDX][2 * jg + 1][1],      \
                      (BBASE) + (uint32_t)(jg * 16 * 128) + bcol[KS]);         \
        } while (0)

    for (int kt = 0; kt < KT; ++kt) {
        if (kt == KT - 1) cp_wait<0>(); else cp_wait<1>();
        __syncthreads();
        if (kt + 2 < KT) load_stage((kt + 2) % 3, kt + 2);

        const uint32_t st = sbase + (kt % 3) * GSTAGE;
        const uint32_t aBase = st + aRowOff;
        const uint32_t bBase = st + bRowOff;

        LOAD_FRAGS(0, aBase, bBase, 0);

        #pragma unroll
        for (int ks = 0; ks < 4; ++ks) {
            const int cur = ks & 1;
            if (ks < 3) {
                if (cur == 0) LOAD_FRAGS(1, aBase, bBase, ks + 1);
                else          LOAD_FRAGS(0, aBase, bBase, ks + 1);
            }
            #pragma unroll
            for (int i = 0; i < 2; ++i)
                #pragma unroll
                for (int j = 0; j < 8; ++j)
                    MMA_BF16(acc[i][j], afr[cur][i], bfr[cur][j]);
        }
    }
    #undef LOAD_FRAGS

    // epilogue
    const float sa = fmaxf(__uint_as_float(g_amax[saslot]), 1e-8f) / 127.f;
    const float sb = fmaxf(__uint_as_float(g_amax[sbslot]), 1e-8f) / 127.f;
    const float s  = sa * sb;

    float lmax = 0.f;
    #pragma unroll
    for (int i = 0; i < 2; ++i) {
        #pragma unroll
        for (int j = 0; j < 8; ++j) {
            const int row0 = rowA0 + wm + i * 16 + (lane >> 2);
            const int col0 = colB0 + wn + j * 8 + (lane & 3) * 2;
            #pragma unroll
            for (int rr = 0; rr < 2; ++rr) {
                const int row = row0 + rr * 8;
                float t0 = fmaf(acc[i][j][rr * 2 + 0], s, bias[col0 + 0]);
                float t1 = fmaf(acc[i][j][rr * 2 + 1], s, bias[col0 + 1]);
                if (EPI == 0) {
                    t0 = 0.5f * t0 * (1.f + erff(t0 * 0.70710678118654752f));
                    t1 = 0.5f * t1 * (1.f + erff(t1 * 0.70710678118654752f));
                    lmax = fmaxf(lmax, fmaxf(fabsf(t0), fabsf(t1)));
                }
                float2 v; v.x = t0; v.y = t1;
                *(float2*)(Cout + (size_t)row * N + col0) = v;
            }
        }
    }
    if (EPI == 0) {
        #pragma unroll
        for (int o = 16; o > 0; o >>= 1)
            lmax = fmaxf(lmax, __shfl_xor_sync(0xffffffffu, lmax, o));
        if (lane == 0) atomicMax(&g_amax[3], __float_as_uint(lmax));
    }
}

#define GEMM_SMEM (3 * GSTAGE)   // 98304 B

// ---------------- launch ----------------------------------------------------
extern "C" void kernel_launch(void* const* d_in, const int* in_sizes, int n_in,
                              void* d_out, int out_size) {
    const float* x  = (const float*)d_in[0];
    const float* w1 = (const float*)d_in[1];
    const float* b1 = (const float*)d_in[2];
    const float* w2 = (const float*)d_in[3];
    const float* b2 = (const float*)d_in[4];
    float* out = (float*)d_out;

    __nv_bfloat16 *xb, *w1b, *w2b, *hb;
    float* hbuf;
    cudaGetSymbolAddress((void**)&xb,   g_xb);
    cudaGetSymbolAddress((void**)&w1b,  g_w1b);
    cudaGetSymbolAddress((void**)&w2b,  g_w2b);
    cudaGetSymbolAddress((void**)&hbuf, g_h);
    cudaGetSymbolAddress((void**)&hb,   g_hb);

    cudaFuncSetAttribute(gemm_bf16_kernel<0>,
                         cudaFuncAttributeMaxDynamicSharedMemorySize, GEMM_SMEM);
    cudaFuncSetAttribute(gemm_bf16_kernel<1>,
                         cudaFuncAttributeMaxDynamicSharedMemorySize, GEMM_SMEM);

    init_kernel<<<1, 32>>>();
    absmax_all_kernel<<<1536, 256>>>((const float4*)x, (const float4*)w1,
                                     (const float4*)w2);
    quant_all_kernel<<<24576, 256>>>((const float4*)x, (const float4*)w1,
                                     (const float4*)w2);
    {
        dim3 grid(H_DIM / 128, M_TOK / 128);
        gemm_bf16_kernel<0><<<grid, 256, GEMM_SMEM>>>(xb, w1b, b1, hbuf,
                                                      D_DIM, H_DIM, 0, 1);
    }
    {
        size_t n4 = ((size_t)M_TOK * H_DIM) / 4;
        quant_h_kernel<<<(unsigned)(n4 / 256), 256>>>((const float4*)hbuf,
                                                      (ushort4*)hb, (int)n4);
    }
    {
        dim3 grid(D_DIM / 128, M_TOK / 128);
        gemm_bf16_kernel<1><<<grid, 256, GEMM_SMEM>>>(hb, w2b, b2, out,
                                                      H_DIM, D_DIM, 3, 2);
    }
    (void)in_sizes; (void)n_in; (void)out_size;
}

// round 12
// speedup vs baseline: 1.0051x; 1.0051x over previous
#include <cuda_runtime.h>
#include <cuda_bf16.h>
#include <cstdint>

#define M_TOK   16384
#define D_DIM   1024
#define H_DIM   4096

// ---------------- scratch (static device memory; no allocations) -----------
__device__ __align__(16) __nv_bfloat16 g_xb [M_TOK * D_DIM];
__device__ __align__(16) __nv_bfloat16 g_w1b[H_DIM * D_DIM];
__device__ __align__(16) __nv_bfloat16 g_w2b[D_DIM * H_DIM];
__device__ __align__(16) float         g_h  [(size_t)M_TOK * H_DIM];
__device__ __align__(16) __nv_bfloat16 g_hb [(size_t)M_TOK * H_DIM];
__device__ unsigned g_amax[4];      // 0: x, 1: w1, 2: w2, 3: h (fp32 bits)

// ---------------- helpers ---------------------------------------------------
__device__ __forceinline__ unsigned smem_u32(const void* p) {
    return (unsigned)__cvta_generic_to_shared(p);
}
__device__ __forceinline__ void cp16(unsigned dst, const void* src) {
    asm volatile("cp.async.cg.shared.global [%0], [%1], 16;\n" :: "r"(dst), "l"(src));
}
__device__ __forceinline__ void cp_commit() {
    asm volatile("cp.async.commit_group;\n");
}
template <int N>
__device__ __forceinline__ void cp_wait() {
    asm volatile("cp.async.wait_group %0;\n" :: "n"(N));
}
__device__ __forceinline__ void ldsm4(unsigned& r0, unsigned& r1, unsigned& r2,
                                      unsigned& r3, unsigned addr) {
    asm volatile("ldmatrix.sync.aligned.m8n8.x4.shared.b16 {%0,%1,%2,%3}, [%4];"
                 : "=r"(r0), "=r"(r1), "=r"(r2), "=r"(r3) : "r"(addr));
}

#define MMA_BF16(d, a, b)                                                      \
    asm volatile(                                                              \
        "mma.sync.aligned.m16n8k16.row.col.f32.bf16.bf16.f32 "                 \
        "{%0,%1,%2,%3},{%4,%5,%6,%7},{%8,%9},{%0,%1,%2,%3};"                   \
        : "+f"(d[0]), "+f"(d[1]), "+f"(d[2]), "+f"(d[3])                       \
        : "r"(a[0]), "r"(a[1]), "r"(a[2]), "r"(a[3]), "r"(b[0]), "r"(b[1]))

// ---------------- fused prep kernels ----------------------------------------
__global__ void init_kernel() {
    if (threadIdx.x < 4) g_amax[threadIdx.x] = 0u;
}

// blocks [0,1024): x | [1024,1280): w1 | [1280,1536): w2
__global__ void absmax_all_kernel(const float4* __restrict__ x,
                                  const float4* __restrict__ w1,
                                  const float4* __restrict__ w2) {
    const float4* p;
    int n4, slot, lb, nb;
    int b = blockIdx.x;
    if (b < 1024)      { p = x;  n4 = (M_TOK * D_DIM) / 4; slot = 0; lb = b;        nb = 1024; }
    else if (b < 1280) { p = w1; n4 = (H_DIM * D_DIM) / 4; slot = 1; lb = b - 1024; nb = 256; }
    else               { p = w2; n4 = (D_DIM * H_DIM) / 4; slot = 2; lb = b - 1280; nb = 256; }

    float m = 0.f;
    for (int i = lb * blockDim.x + threadIdx.x; i < n4; i += nb * blockDim.x) {
        float4 v = p[i];
        m = fmaxf(m, fmaxf(fmaxf(fabsf(v.x), fabsf(v.y)),
                           fmaxf(fabsf(v.z), fabsf(v.w))));
    }
    #pragma unroll
    for (int o = 16; o > 0; o >>= 1)
        m = fmaxf(m, __shfl_xor_sync(0xffffffffu, m, o));
    __shared__ float sm[8];
    if ((threadIdx.x & 31) == 0) sm[threadIdx.x >> 5] = m;
    __syncthreads();
    if (threadIdx.x == 0) {
        float v = sm[0];
        #pragma unroll
        for (int i = 1; i < 8; ++i) v = fmaxf(v, sm[i]);
        atomicMax(&g_amax[slot], __float_as_uint(v));
    }
}

__device__ __forceinline__ float quantf(float v, float scale) {
    return fminf(fmaxf(rintf(v / scale), -127.f), 127.f);
}
__device__ __forceinline__ unsigned short bf16bits(float v) {
    __nv_bfloat16 h = __float2bfloat16(v);
    return *(unsigned short*)&h;
}

// blocks [0,16384): x | [16384,20480): w1 | [20480,24576): w2  (all -> bf16 ints)
__global__ void quant_all_kernel(const float4* __restrict__ x,
                                 const float4* __restrict__ w1,
                                 const float4* __restrict__ w2) {
    int b = blockIdx.x;
    const float4* src;
    ushort4* dst;
    int i, slot;
    if (b < 16384)      { src = x;  dst = (ushort4*)g_xb;  i = b * blockDim.x + threadIdx.x;            slot = 0; }
    else if (b < 20480) { src = w1; dst = (ushort4*)g_w1b; i = (b - 16384) * blockDim.x + threadIdx.x;  slot = 1; }
    else                { src = w2; dst = (ushort4*)g_w2b; i = (b - 20480) * blockDim.x + threadIdx.x;  slot = 2; }
    float scale = fmaxf(__uint_as_float(g_amax[slot]), 1e-8f) / 127.f;
    float4 v = src[i];
    ushort4 o;
    o.x = bf16bits(quantf(v.x, scale));
    o.y = bf16bits(quantf(v.y, scale));
    o.z = bf16bits(quantf(v.z, scale));
    o.w = bf16bits(quantf(v.w, scale));
    dst[i] = o;
}

__global__ void quant_h_kernel(const float4* __restrict__ x,
                               ushort4* __restrict__ q, int n4) {
    float scale = fmaxf(__uint_as_float(g_amax[3]), 1e-8f) / 127.f;
    int i = blockIdx.x * blockDim.x + threadIdx.x;
    if (i < n4) {
        float4 v = x[i];
        ushort4 o;
        o.x = bf16bits(quantf(v.x, scale));
        o.y = bf16bits(quantf(v.y, scale));
        o.z = bf16bits(quantf(v.z, scale));
        o.w = bf16bits(quantf(v.w, scale));
        q[i] = o;
    }
}

// ---------------- bf16 GEMM (block 256x128, 8 warps 64x64, staggered) --------
// C[M,N] = A[M,K](bf16 row-major) * B[N,K](bf16 row-major as col-major op)
// 256 threads, warp grid 4(M) x 2(N), warp tile 64x64, BK=64 (128B).
// SMSP k hosts warps k and k+4 (different N-columns). The N-col-1 warps
// process the four k16 slabs in rotated order so their LDSM windows overlap
// the other warp's MMA bursts -> tensor pipe bubbles filled.
// 3-stage ring, stage = 256*128 (A) + 128*128 (B) = 48KB, 144KB total.
#define GSTAGE  49152
#define GB_OFF  32768

template <int EPI>
__global__ __launch_bounds__(256, 1)
void gemm_bf16_kernel(const __nv_bfloat16* __restrict__ A,
                      const __nv_bfloat16* __restrict__ B,
                      const float* __restrict__ bias,
                      float* __restrict__ Cout,
                      int K, int N, int saslot, int sbslot) {
    extern __shared__ __align__(128) char smem[];
    const uint32_t sbase = smem_u32(smem);

    const int tid  = threadIdx.x;
    const int lane = tid & 31;
    const int warp = tid >> 5;
    const int wm = (warp & 3) * 64;    // 4 warp rows (M)
    const int wn = (warp >> 2) * 64;   // 2 warp cols (N)
    const int koff = (warp >> 2) << 1; // ks rotation: col-1 warps offset by 2

    const int rowA0 = blockIdx.y * 256;
    const int colB0 = blockIdx.x * 128;

    float acc[4][8][4];
    #pragma unroll
    for (int i = 0; i < 4; ++i)
        #pragma unroll
        for (int j = 0; j < 8; ++j)
            #pragma unroll
            for (int r = 0; r < 4; ++r) acc[i][j][r] = 0.f;

    const int KT = K >> 6;
    const size_t Kb = (size_t)K * 2;

    // loader: A 256 rows x 8 chunks (2048) + B 128 rows x 8 chunks (1024)
    // = 3072 chunks over 256 threads -> 12 per thread.
    const int ld_row = tid >> 3;            // 0..31
    const int ld_c16 = (tid & 7) << 4;
    auto load_stage = [&](int st, int kt) {
        const uint32_t stoff = sbase + st * GSTAGE;
        const size_t k0b = (size_t)kt * 128;
        const char* Ab = (const char*)A + (size_t)rowA0 * Kb + k0b + ld_c16;
        const char* Bb = (const char*)B + (size_t)colB0 * Kb + k0b + ld_c16;
        #pragma unroll
        for (int m = 0; m < 8; ++m) {
            const int row = (m << 5) + ld_row;
            const uint32_t sw = (uint32_t)(row * 128 + (ld_c16 ^ ((row & 7) << 4)));
            cp16(stoff + sw, Ab + (size_t)row * Kb);
            if (m < 4)
                cp16(stoff + GB_OFF + sw, Bb + (size_t)row * Kb);
        }
        cp_commit();
    };

    load_stage(0, 0);
    load_stage(1, 1);

    // ldmatrix lane geometry
    const int a_row = lane & 15;
    const int a_sel = (lane >> 4) << 4;
    const int b_row = (lane & 7) + (((lane >> 3) & 1) << 3);
    const int b_sel = (lane >> 4) << 4;
    const uint32_t a_swx = (uint32_t)((a_row & 7) << 4);
    const uint32_t b_swx = (uint32_t)((b_row & 7) << 4);
    uint32_t acol[4], bcol[4];
    #pragma unroll
    for (int ks = 0; ks < 4; ++ks) {
        const int kss = (ks + koff) & 3;   // rotated slab order per warp column
        acol[ks] = (uint32_t)((kss * 32 + a_sel) ^ a_swx);
        bcol[ks] = (uint32_t)((kss * 32 + b_sel) ^ b_swx);
    }
    const uint32_t aRowOff = (uint32_t)((wm + a_row) * 128);
    const uint32_t bRowOff = (uint32_t)(GB_OFF + (wn + b_row) * 128);

    for (int kt = 0; kt < KT; ++kt) {
        if (kt == KT - 1) cp_wait<0>(); else cp_wait<1>();
        __syncthreads();
        if (kt + 2 < KT) load_stage((kt + 2) % 3, kt + 2);

        const uint32_t st = sbase + (kt % 3) * GSTAGE;
        const uint32_t aBase = st + aRowOff;
        const uint32_t bBase = st + bRowOff;

        #pragma unroll
        for (int ks = 0; ks < 4; ++ks) {
            unsigned a[4][4], b[8][2];
            #pragma unroll
            for (int i = 0; i < 4; ++i)
                ldsm4(a[i][0], a[i][1], a[i][2], a[i][3],
                      aBase + (uint32_t)(i * 16 * 128) + acol[ks]);
            #pragma unroll
            for (int jg = 0; jg < 4; ++jg)
                ldsm4(b[2 * jg][0], b[2 * jg + 1][0],
                      b[2 * jg][1], b[2 * jg + 1][1],
                      bBase + (uint32_t)(jg * 16 * 128) + bcol[ks]);
            #pragma unroll
            for (int i = 0; i < 4; ++i)
                #pragma unroll
                for (int j = 0; j < 8; ++j)
                    MMA_BF16(acc[i][j], a[i], b[j]);
        }
    }

    // epilogue
    const float sa = fmaxf(__uint_as_float(g_amax[saslot]), 1e-8f) / 127.f;
    const float sb = fmaxf(__uint_as_float(g_amax[sbslot]), 1e-8f) / 127.f;
    const float s  = sa * sb;

    float lmax = 0.f;
    #pragma unroll
    for (int i = 0; i < 4; ++i) {
        #pragma unroll
        for (int j = 0; j < 8; ++j) {
            const int row0 = rowA0 + wm + i * 16 + (lane >> 2);
            const int col0 = colB0 + wn + j * 8 + (lane & 3) * 2;
            #pragma unroll
            for (int rr = 0; rr < 2; ++rr) {
                const int row = row0 + rr * 8;
                float t0 = fmaf(acc[i][j][rr * 2 + 0], s, bias[col0 + 0]);
                float t1 = fmaf(acc[i][j][rr * 2 + 1], s, bias[col0 + 1]);
                if (EPI == 0) {
                    t0 = 0.5f * t0 * (1.f + erff(t0 * 0.70710678118654752f));
                    t1 = 0.5f * t1 * (1.f + erff(t1 * 0.70710678118654752f));
                    lmax = fmaxf(lmax, fmaxf(fabsf(t0), fabsf(t1)));
                }
                float2 v; v.x = t0; v.y = t1;
                *(float2*)(Cout + (size_t)row * N + col0) = v;
            }
        }
    }
    if (EPI == 0) {
        #pragma unroll
        for (int o = 16; o > 0; o >>= 1)
            lmax = fmaxf(lmax, __shfl_xor_sync(0xffffffffu, lmax, o));
        if (lane == 0) atomicMax(&g_amax[3], __float_as_uint(lmax));
    }
}

#define GEMM_SMEM (3 * GSTAGE)   // 147456 B

// ---------------- launch ----------------------------------------------------
extern "C" void kernel_launch(void* const* d_in, const int* in_sizes, int n_in,
                              void* d_out, int out_size) {
    const float* x  = (const float*)d_in[0];
    const float* w1 = (const float*)d_in[1];
    const float* b1 = (const float*)d_in[2];
    const float* w2 = (const float*)d_in[3];
    const float* b2 = (const float*)d_in[4];
    float* out = (float*)d_out;

    __nv_bfloat16 *xb, *w1b, *w2b, *hb;
    float* hbuf;
    cudaGetSymbolAddress((void**)&xb,   g_xb);
    cudaGetSymbolAddress((void**)&w1b,  g_w1b);
    cudaGetSymbolAddress((void**)&w2b,  g_w2b);
    cudaGetSymbolAddress((void**)&hbuf, g_h);
    cudaGetSymbolAddress((void**)&hb,   g_hb);

    cudaFuncSetAttribute(gemm_bf16_kernel<0>,
                         cudaFuncAttributeMaxDynamicSharedMemorySize, GEMM_SMEM);
    cudaFuncSetAttribute(gemm_bf16_kernel<1>,
                         cudaFuncAttributeMaxDynamicSharedMemorySize, GEMM_SMEM);

    init_kernel<<<1, 32>>>();
    absmax_all_kernel<<<1536, 256>>>((const float4*)x, (const float4*)w1,
                                     (const float4*)w2);
    quant_all_kernel<<<24576, 256>>>((const float4*)x, (const float4*)w1,
                                     (const float4*)w2);
    {
        dim3 grid(H_DIM / 128, M_TOK / 256);
        gemm_bf16_kernel<0><<<grid, 256, GEMM_SMEM>>>(xb, w1b, b1, hbuf,
                                                      D_DIM, H_DIM, 0, 1);
    }
    {
        size_t n4 = ((size_t)M_TOK * H_DIM) / 4;
        quant_h_kernel<<<(unsigned)(n4 / 256), 256>>>((const float4*)hbuf,
                                                      (ushort4*)hb, (int)n4);
    }
    {
        dim3 grid(D_DIM / 128, M_TOK / 256);
        gemm_bf16_kernel<1><<<grid, 256, GEMM_SMEM>>>(hb, w2b, b2, out,
                                                      H_DIM, D_DIM, 3, 2);
    }
    (void)in_sizes; (void)n_in; (void)out_size;
}

// round 13
// speedup vs baseline: 1.1434x; 1.1377x over previous
#include <cuda_runtime.h>
#include <cuda_fp16.h>
#include <cstdint>

#define M_TOK   16384
#define D_DIM   1024
#define H_DIM   4096

// ---------------- scratch (static device memory; no allocations) -----------
__device__ __align__(16) __half g_xh [M_TOK * D_DIM];
__device__ __align__(16) __half g_w1h[H_DIM * D_DIM];
__device__ __align__(16) __half g_w2h[D_DIM * H_DIM];
__device__ __align__(16) float  g_h  [(size_t)M_TOK * H_DIM];
__device__ __align__(16) __half g_hh [(size_t)M_TOK * H_DIM];
__device__ unsigned g_amax[4];      // 0: x, 1: w1, 2: w2, 3: h (fp32 bits)

// ---------------- helpers ---------------------------------------------------
__device__ __forceinline__ unsigned smem_u32(const void* p) {
    return (unsigned)__cvta_generic_to_shared(p);
}
__device__ __forceinline__ void cp16(unsigned dst, const void* src) {
    asm volatile("cp.async.cg.shared.global [%0], [%1], 16;\n" :: "r"(dst), "l"(src));
}
__device__ __forceinline__ void cp_commit() {
    asm volatile("cp.async.commit_group;\n");
}
template <int N>
__device__ __forceinline__ void cp_wait() {
    asm volatile("cp.async.wait_group %0;\n" :: "n"(N));
}
__device__ __forceinline__ void ldsm4(unsigned& r0, unsigned& r1, unsigned& r2,
                                      unsigned& r3, unsigned addr) {
    asm volatile("ldmatrix.sync.aligned.m8n8.x4.shared.b16 {%0,%1,%2,%3}, [%4];"
                 : "=r"(r0), "=r"(r1), "=r"(r2), "=r"(r3) : "r"(addr));
}

#define MMA_F16(d, a, b)                                                       \
    asm volatile(                                                              \
        "mma.sync.aligned.m16n8k16.row.col.f32.f16.f16.f32 "                   \
        "{%0,%1,%2,%3},{%4,%5,%6,%7},{%8,%9},{%0,%1,%2,%3};"                   \
        : "+f"(d[0]), "+f"(d[1]), "+f"(d[2]), "+f"(d[3])                       \
        : "r"(a[0]), "r"(a[1]), "r"(a[2]), "r"(a[3]), "r"(b[0]), "r"(b[1]))

// ---------------- fused prep kernels ----------------------------------------
__global__ void init_kernel() {
    if (threadIdx.x < 4) g_amax[threadIdx.x] = 0u;
}

// blocks [0,1024): x | [1024,1280): w1 | [1280,1536): w2
__global__ void absmax_all_kernel(const float4* __restrict__ x,
                                  const float4* __restrict__ w1,
                                  const float4* __restrict__ w2) {
    const float4* p;
    int n4, slot, lb, nb;
    int b = blockIdx.x;
    if (b < 1024)      { p = x;  n4 = (M_TOK * D_DIM) / 4; slot = 0; lb = b;        nb = 1024; }
    else if (b < 1280) { p = w1; n4 = (H_DIM * D_DIM) / 4; slot = 1; lb = b - 1024; nb = 256; }
    else               { p = w2; n4 = (D_DIM * H_DIM) / 4; slot = 2; lb = b - 1280; nb = 256; }

    float m0 = 0.f, m1 = 0.f;
    const int stride = nb * blockDim.x;
    int i = lb * blockDim.x + threadIdx.x;
    for (; i + stride < n4; i += 2 * stride) {
        float4 v = p[i];
        float4 w = p[i + stride];
        m0 = fmaxf(m0, fmaxf(fmaxf(fabsf(v.x), fabsf(v.y)),
                             fmaxf(fabsf(v.z), fabsf(v.w))));
        m1 = fmaxf(m1, fmaxf(fmaxf(fabsf(w.x), fabsf(w.y)),
                             fmaxf(fabsf(w.z), fabsf(w.w))));
    }
    if (i < n4) {
        float4 v = p[i];
        m0 = fmaxf(m0, fmaxf(fmaxf(fabsf(v.x), fabsf(v.y)),
                             fmaxf(fabsf(v.z), fabsf(v.w))));
    }
    float m = fmaxf(m0, m1);
    #pragma unroll
    for (int o = 16; o > 0; o >>= 1)
        m = fmaxf(m, __shfl_xor_sync(0xffffffffu, m, o));
    __shared__ float sm[8];
    if ((threadIdx.x & 31) == 0) sm[threadIdx.x >> 5] = m;
    __syncthreads();
    if (threadIdx.x == 0) {
        float v = sm[0];
        #pragma unroll
        for (int i2 = 1; i2 < 8; ++i2) v = fmaxf(v, sm[i2]);
        atomicMax(&g_amax[slot], __float_as_uint(v));
    }
}

__device__ __forceinline__ float quantf(float v, float scale) {
    return fminf(fmaxf(rintf(v / scale), -127.f), 127.f);
}
__device__ __forceinline__ unsigned short h16bits(float v) {
    __half h = __float2half_rn(v);
    return *(unsigned short*)&h;
}
__device__ __forceinline__ ushort4 quant4(float4 v, float scale) {
    ushort4 o;
    o.x = h16bits(quantf(v.x, scale));
    o.y = h16bits(quantf(v.y, scale));
    o.z = h16bits(quantf(v.z, scale));
    o.w = h16bits(quantf(v.w, scale));
    return o;
}

// blocks [0,16384): x | [16384,20480): w1 | [20480,24576): w2  (all -> fp16 ints)
__global__ void quant_all_kernel(const float4* __restrict__ x,
                                 const float4* __restrict__ w1,
                                 const float4* __restrict__ w2) {
    int b = blockIdx.x;
    const float4* src;
    ushort4* dst;
    int i, slot;
    if (b < 16384)      { src = x;  dst = (ushort4*)g_xh;  i = b * blockDim.x + threadIdx.x;            slot = 0; }
    else if (b < 20480) { src = w1; dst = (ushort4*)g_w1h; i = (b - 16384) * blockDim.x + threadIdx.x;  slot = 1; }
    else                { src = w2; dst = (ushort4*)g_w2h; i = (b - 20480) * blockDim.x + threadIdx.x;  slot = 2; }
    float scale = fmaxf(__uint_as_float(g_amax[slot]), 1e-8f) / 127.f;
    dst[i] = quant4(src[i], scale);
}

// 2 float4 per thread for MLP
__global__ void quant_h_kernel(const float4* __restrict__ x,
                               ushort4* __restrict__ q, int n4) {
    float scale = fmaxf(__uint_as_float(g_amax[3]), 1e-8f) / 127.f;
    int i0 = blockIdx.x * (blockDim.x * 2) + threadIdx.x;
    int i1 = i0 + blockDim.x;
    float4 v0, v1;
    bool p0 = i0 < n4, p1 = i1 < n4;
    if (p0) v0 = x[i0];
    if (p1) v1 = x[i1];
    if (p0) q[i0] = quant4(v0, scale);
    if (p1) q[i1] = quant4(v1, scale);
}

// ---------------- fp16 GEMM (R7 structure: warp 64x64, BK=64, 3-stage) -------
// C[M,N] = A[M,K](f16 row-major) * B[N,K](f16 row-major as col-major op)
// Block 128x128, 128 threads (4 warps, 2x2), warp tile 64x64, BK=64 (128B).
// Smem: XOR swizzle, stride 128B, stage = 32KB, 3 stages = 96KB dynamic.
#define GSTAGE  32768
#define GB_OFF  16384

template <int EPI>
__global__ __launch_bounds__(128, 2)
void gemm_f16_kernel(const __half* __restrict__ A,
                     const __half* __restrict__ B,
                     const float* __restrict__ bias,
                     float* __restrict__ Cout,
                     int K, int N, int saslot, int sbslot) {
    extern __shared__ __align__(128) char smem[];
    const uint32_t sbase = smem_u32(smem);

    const int tid  = threadIdx.x;
    const int lane = tid & 31;
    const int warp = tid >> 5;
    const int wm = (warp >> 1) * 64;
    const int wn = (warp & 1) * 64;

    const int rowA0 = blockIdx.y * 128;
    const int colB0 = blockIdx.x * 128;

    float acc[4][8][4];
    #pragma unroll
    for (int i = 0; i < 4; ++i)
        #pragma unroll
        for (int j = 0; j < 8; ++j)
            #pragma unroll
            for (int r = 0; r < 4; ++r) acc[i][j][r] = 0.f;

    const int KT = K >> 6;
    const size_t Kb = (size_t)K * 2;

    const int ld_row = tid >> 3;
    const int ld_c16 = (tid & 7) << 4;
    auto load_stage = [&](int st, int kt) {
        const uint32_t stoff = sbase + st * GSTAGE;
        const size_t k0b = (size_t)kt * 128;
        const char* Ab = (const char*)A + (size_t)rowA0 * Kb + k0b + ld_c16;
        const char* Bb = (const char*)B + (size_t)colB0 * Kb + k0b + ld_c16;
        #pragma unroll
        for (int m = 0; m < 8; ++m) {
            const int row = (m << 4) + ld_row;
            const uint32_t sw = (uint32_t)(row * 128 + (ld_c16 ^ ((row & 7) << 4)));
            cp16(stoff + sw,          Ab + (size_t)row * Kb);
            cp16(stoff + GB_OFF + sw, Bb + (size_t)row * Kb);
        }
        cp_commit();
    };

    load_stage(0, 0);
    load_stage(1, 1);

    const int a_row = lane & 15;
    const int a_sel = (lane >> 4) << 4;
    const int b_row = (lane & 7) + (((lane >> 3) & 1) << 3);
    const int b_sel = (lane >> 4) << 4;
    const uint32_t a_swx = (uint32_t)((a_row & 7) << 4);
    const uint32_t b_swx = (uint32_t)((b_row & 7) << 4);
    uint32_t acol[4], bcol[4];
    #pragma unroll
    for (int ks = 0; ks < 4; ++ks) {
        acol[ks] = (uint32_t)((ks * 32 + a_sel) ^ a_swx);
        bcol[ks] = (uint32_t)((ks * 32 + b_sel) ^ b_swx);
    }
    const uint32_t aRowOff = (uint32_t)((wm + a_row) * 128);
    const uint32_t bRowOff = (uint32_t)(GB_OFF + (wn + b_row) * 128);

    for (int kt = 0; kt < KT; ++kt) {
        if (kt == KT - 1) cp_wait<0>(); else cp_wait<1>();
        __syncthreads();
        if (kt + 2 < KT) load_stage((kt + 2) % 3, kt + 2);

        const uint32_t st = sbase + (kt % 3) * GSTAGE;
        const uint32_t aBase = st + aRowOff;
        const uint32_t bBase = st + bRowOff;

        #pragma unroll
        for (int ks = 0; ks < 4; ++ks) {
            unsigned a[4][4], b[8][2];
            #pragma unroll
            for (int i = 0; i < 4; ++i)
                ldsm4(a[i][0], a[i][1], a[i][2], a[i][3],
                      aBase + (uint32_t)(i * 16 * 128) + acol[ks]);
            #pragma unroll
            for (int jg = 0; jg < 4; ++jg)
                ldsm4(b[2 * jg][0], b[2 * jg + 1][0],
                      b[2 * jg][1], b[2 * jg + 1][1],
                      bBase + (uint32_t)(jg * 16 * 128) + bcol[ks]);
            #pragma unroll
            for (int i = 0; i < 4; ++i)
                #pragma unroll
                for (int j = 0; j < 8; ++j)
                    MMA_F16(acc[i][j], a[i], b[j]);
        }
    }

    // epilogue
    const float sa = fmaxf(__uint_as_float(g_amax[saslot]), 1e-8f) / 127.f;
    const float sb = fmaxf(__uint_as_float(g_amax[sbslot]), 1e-8f) / 127.f;
    const float s  = sa * sb;

    float lmax = 0.f;
    #pragma unroll
    for (int i = 0; i < 4; ++i) {
        #pragma unroll
        for (int j = 0; j < 8; ++j) {
            const int row0 = rowA0 + wm + i * 16 + (lane >> 2);
            const int col0 = colB0 + wn + j * 8 + (lane & 3) * 2;
            #pragma unroll
            for (int rr = 0; rr < 2; ++rr) {
                const int row = row0 + rr * 8;
                float t0 = fmaf(acc[i][j][rr * 2 + 0], s, bias[col0 + 0]);
                float t1 = fmaf(acc[i][j][rr * 2 + 1], s, bias[col0 + 1]);
                if (EPI == 0) {
                    t0 = 0.5f * t0 * (1.f + erff(t0 * 0.70710678118654752f));
                    t1 = 0.5f * t1 * (1.f + erff(t1 * 0.70710678118654752f));
                    lmax = fmaxf(lmax, fmaxf(fabsf(t0), fabsf(t1)));
                }
                float2 v; v.x = t0; v.y = t1;
                *(float2*)(Cout + (size_t)row * N + col0) = v;
            }
        }
    }
    if (EPI == 0) {
        #pragma unroll
        for (int o = 16; o > 0; o >>= 1)
            lmax = fmaxf(lmax, __shfl_xor_sync(0xffffffffu, lmax, o));
        if (lane == 0) atomicMax(&g_amax[3], __float_as_uint(lmax));
    }
}

#define GEMM_SMEM (3 * GSTAGE)   // 98304 B

// ---------------- launch ----------------------------------------------------
extern "C" void kernel_launch(void* const* d_in, const int* in_sizes, int n_in,
                              void* d_out, int out_size) {
    const float* x  = (const float*)d_in[0];
    const float* w1 = (const float*)d_in[1];
    const float* b1 = (const float*)d_in[2];
    const float* w2 = (const float*)d_in[3];
    const float* b2 = (const float*)d_in[4];
    float* out = (float*)d_out;

    __half *xh, *w1h, *w2h, *hh;
    float* hbuf;
    cudaGetSymbolAddress((void**)&xh,   g_xh);
    cudaGetSymbolAddress((void**)&w1h,  g_w1h);
    cudaGetSymbolAddress((void**)&w2h,  g_w2h);
    cudaGetSymbolAddress((void**)&hbuf, g_h);
    cudaGetSymbolAddress((void**)&hh,   g_hh);

    cudaFuncSetAttribute(gemm_f16_kernel<0>,
                         cudaFuncAttributeMaxDynamicSharedMemorySize, GEMM_SMEM);
    cudaFuncSetAttribute(gemm_f16_kernel<1>,
                         cudaFuncAttributeMaxDynamicSharedMemorySize, GEMM_SMEM);

    init_kernel<<<1, 32>>>();
    absmax_all_kernel<<<1536, 256>>>((const float4*)x, (const float4*)w1,
                                     (const float4*)w2);
    quant_all_kernel<<<24576, 256>>>((const float4*)x, (const float4*)w1,
                                     (const float4*)w2);
    {
        dim3 grid(H_DIM / 128, M_TOK / 128);
        gemm_f16_kernel<0><<<grid, 128, GEMM_SMEM>>>(xh, w1h, b1, hbuf,
                                                     D_DIM, H_DIM, 0, 1);
    }
    {
        int n4 = (int)(((size_t)M_TOK * H_DIM) / 4);
        quant_h_kernel<<<(n4 + 511) / 512, 256>>>((const float4*)hbuf,
                                                  (ushort4*)hh, n4);
    }
    {
        dim3 grid(D_DIM / 128, M_TOK / 128);
        gemm_f16_kernel<1><<<grid, 128, GEMM_SMEM>>>(hh, w2h, b2, out,
                                                     H_DIM, D_DIM, 3, 2);
    }
    (void)in_sizes; (void)n_in; (void)out_size;
}

// round 15
// speedup vs baseline: 1.1451x; 1.0015x over previous
#include <cuda_runtime.h>
#include <cuda_fp16.h>
#include <cstdint>

#define M_TOK   16384
#define D_DIM   1024
#define H_DIM   4096

// ---------------- scratch (static device memory; no allocations) -----------
__device__ __align__(16) __half g_xh [M_TOK * D_DIM];
__device__ __align__(16) __half g_w1h[H_DIM * D_DIM];
__device__ __align__(16) __half g_w2h[D_DIM * H_DIM];
__device__ __align__(16) float  g_h  [(size_t)M_TOK * H_DIM];   // gelu(h) fp32
__device__ __align__(16) __half g_hh [(size_t)M_TOK * H_DIM];   // quantized h
__device__ unsigned g_amax[4];      // 0: x, 1: w1, 2: w2, 3: h (fp32 bits)

// ---------------- helpers ---------------------------------------------------
__device__ __forceinline__ unsigned smem_u32(const void* p) {
    return (unsigned)__cvta_generic_to_shared(p);
}
__device__ __forceinline__ void cp16(unsigned dst, const void* src) {
    asm volatile("cp.async.cg.shared.global [%0], [%1], 16;\n" :: "r"(dst), "l"(src));
}
__device__ __forceinline__ void cp_commit() {
    asm volatile("cp.async.commit_group;\n");
}
template <int N>
__device__ __forceinline__ void cp_wait() {
    asm volatile("cp.async.wait_group %0;\n" :: "n"(N));
}
__device__ __forceinline__ void ldsm4(unsigned& r0, unsigned& r1, unsigned& r2,
                                      unsigned& r3, unsigned addr) {
    asm volatile("ldmatrix.sync.aligned.m8n8.x4.shared.b16 {%0,%1,%2,%3}, [%4];"
                 : "=r"(r0), "=r"(r1), "=r"(r2), "=r"(r3) : "r"(addr));
}

#define MMA_F16(d, a, b)                                                       \
    asm volatile(                                                              \
        "mma.sync.aligned.m16n8k16.row.col.f32.f16.f16.f32 "                   \
        "{%0,%1,%2,%3},{%4,%5,%6,%7},{%8,%9},{%0,%1,%2,%3};"                   \
        : "+f"(d[0]), "+f"(d[1]), "+f"(d[2]), "+f"(d[3])                       \
        : "r"(a[0]), "r"(a[1]), "r"(a[2]), "r"(a[3]), "r"(b[0]), "r"(b[1]))

// ---------------- fused prep kernels ----------------------------------------
__global__ void init_kernel() {
    if (threadIdx.x < 4) g_amax[threadIdx.x] = 0u;
}

// blocks [0,1024): x | [1024,1280): w1 | [1280,1536): w2
__global__ void absmax_all_kernel(const float4* __restrict__ x,
                                  const float4* __restrict__ w1,
                                  const float4* __restrict__ w2) {
    const float4* p;
    int n4, slot, lb, nb;
    int b = blockIdx.x;
    if (b < 1024)      { p = x;  n4 = (M_TOK * D_DIM) / 4; slot = 0; lb = b;        nb = 1024; }
    else if (b < 1280) { p = w1; n4 = (H_DIM * D_DIM) / 4; slot = 1; lb = b - 1024; nb = 256; }
    else               { p = w2; n4 = (D_DIM * H_DIM) / 4; slot = 2; lb = b - 1280; nb = 256; }

    float m0 = 0.f, m1 = 0.f;
    const int stride = nb * blockDim.x;
    int i = lb * blockDim.x + threadIdx.x;
    for (; i + stride < n4; i += 2 * stride) {
        float4 v = p[i];
        float4 w = p[i + stride];
        m0 = fmaxf(m0, fmaxf(fmaxf(fabsf(v.x), fabsf(v.y)),
                             fmaxf(fabsf(v.z), fabsf(v.w))));
        m1 = fmaxf(m1, fmaxf(fmaxf(fabsf(w.x), fabsf(w.y)),
                             fmaxf(fabsf(w.z), fabsf(w.w))));
    }
    if (i < n4) {
        float4 v = p[i];
        m0 = fmaxf(m0, fmaxf(fmaxf(fabsf(v.x), fabsf(v.y)),
                             fmaxf(fabsf(v.z), fabsf(v.w))));
    }
    float m = fmaxf(m0, m1);
    #pragma unroll
    for (int o = 16; o > 0; o >>= 1)
        m = fmaxf(m, __shfl_xor_sync(0xffffffffu, m, o));
    __shared__ float sm[8];
    if ((threadIdx.x & 31) == 0) sm[threadIdx.x >> 5] = m;
    __syncthreads();
    if (threadIdx.x == 0) {
        float v = sm[0];
        #pragma unroll
        for (int i2 = 1; i2 < 8; ++i2) v = fmaxf(v, sm[i2]);
        atomicMax(&g_amax[slot], __float_as_uint(v));
    }
}

__device__ __forceinline__ float quantf(float v, float scale) {
    return fminf(fmaxf(rintf(v / scale), -127.f), 127.f);
}
__device__ __forceinline__ unsigned short h16bits(float v) {
    __half h = __float2half_rn(v);
    return *(unsigned short*)&h;
}
__device__ __forceinline__ ushort4 quant4(float4 v, float scale) {
    ushort4 o;
    o.x = h16bits(quantf(v.x, scale));
    o.y = h16bits(quantf(v.y, scale));
    o.z = h16bits(quantf(v.z, scale));
    o.w = h16bits(quantf(v.w, scale));
    return o;
}

// blocks [0,16384): x | [16384,20480): w1 | [20480,24576): w2  (all -> fp16 ints)
__global__ void quant_all_kernel(const float4* __restrict__ x,
                                 const float4* __restrict__ w1,
                                 const float4* __restrict__ w2) {
    int b = blockIdx.x;
    const float4* src;
    ushort4* dst;
    int i, slot;
    if (b < 16384)      { src = x;  dst = (ushort4*)g_xh;  i = b * blockDim.x + threadIdx.x;            slot = 0; }
    else if (b < 20480) { src = w1; dst = (ushort4*)g_w1h; i = (b - 16384) * blockDim.x + threadIdx.x;  slot = 1; }
    else                { src = w2; dst = (ushort4*)g_w2h; i = (b - 20480) * blockDim.x + threadIdx.x;  slot = 2; }
    float scale = fmaxf(__uint_as_float(g_amax[slot]), 1e-8f) / 127.f;
    dst[i] = quant4(src[i], scale);
}

// 2 float4 per thread (MLP) : fp32 h -> quantized fp16
__global__ void quant_h_kernel(const float4* __restrict__ x,
                               ushort4* __restrict__ q, int n4) {
    float scale = fmaxf(__uint_as_float(g_amax[3]), 1e-8f) / 127.f;
    int i0 = blockIdx.x * (blockDim.x * 2) + threadIdx.x;
    int i1 = i0 + blockDim.x;
    float4 v0, v1;
    bool p0 = i0 < n4, p1 = i1 < n4;
    if (p0) v0 = x[i0];
    if (p1) v1 = x[i1];
    if (p0) q[i0] = quant4(v0, scale);
    if (p1) q[i1] = quant4(v1, scale);
}

// ---------------- fp16 GEMM (R7 structure + per-CTA ks stagger) --------------
// C[M,N] = A[M,K](f16 row-major) * B[N,K](f16 row-major as col-major op)
// Block 128x128, 128 threads (4 warps, 2x2), warp tile 64x64, BK=64 (128B).
// Smem: XOR swizzle, stride 128B, stage = 32KB, 3 stages = 96KB dynamic.
// Co-resident CTAs (bid vs bid+148) differ in (blockIdx.x>>2)&1 -> their k16
// slab order is rotated by 2 so LDSM windows of one CTA's warps overlap the
// other CTA's MMA bursts on each SMSP.
#define GSTAGE  32768
#define GB_OFF  16384

template <int EPI>
__global__ __launch_bounds__(128, 2)
void gemm_f16_kernel(const __half* __restrict__ A,
                     const __half* __restrict__ B,
                     const float* __restrict__ bias,
                     float* __restrict__ Cout,
                     int K, int N, int saslot, int sbslot) {
    extern __shared__ __align__(128) char smem[];
    const uint32_t sbase = smem_u32(smem);

    const int tid  = threadIdx.x;
    const int lane = tid & 31;
    const int warp = tid >> 5;
    const int wm = (warp >> 1) * 64;
    const int wn = (warp & 1) * 64;
    const int koff = ((blockIdx.x >> 2) & 1) << 1;   // 0 or 2

    const int rowA0 = blockIdx.y * 128;
    const int colB0 = blockIdx.x * 128;

    float acc[4][8][4];
    #pragma unroll
    for (int i = 0; i < 4; ++i)
        #pragma unroll
        for (int j = 0; j < 8; ++j)
            #pragma unroll
            for (int r = 0; r < 4; ++r) acc[i][j][r] = 0.f;

    const int KT = K >> 6;
    const size_t Kb = (size_t)K * 2;

    const int ld_row = tid >> 3;
    const int ld_c16 = (tid & 7) << 4;
    auto load_stage = [&](int st, int kt) {
        const uint32_t stoff = sbase + st * GSTAGE;
        const size_t k0b = (size_t)kt * 128;
        const char* Ab = (const char*)A + (size_t)rowA0 * Kb + k0b + ld_c16;
        const char* Bb = (const char*)B + (size_t)colB0 * Kb + k0b + ld_c16;
        #pragma unroll
        for (int m = 0; m < 8; ++m) {
            const int row = (m << 4) + ld_row;
            const uint32_t sw = (uint32_t)(row * 128 + (ld_c16 ^ ((row & 7) << 4)));
            cp16(stoff + sw,          Ab + (size_t)row * Kb);
            cp16(stoff + GB_OFF + sw, Bb + (size_t)row * Kb);
        }
        cp_commit();
    };

    load_stage(0, 0);
    load_stage(1, 1);

    const int a_row = lane & 15;
    const int a_sel = (lane >> 4) << 4;
    const int b_row = (lane & 7) + (((lane >> 3) & 1) << 3);
    const int b_sel = (lane >> 4) << 4;
    const uint32_t a_swx = (uint32_t)((a_row & 7) << 4);
    const uint32_t b_swx = (uint32_t)((b_row & 7) << 4);
    uint32_t acol[4], bcol[4];
    #pragma unroll
    for (int ks = 0; ks < 4; ++ks) {
        const int kss = (ks + koff) & 3;    // per-CTA rotated slab order
        acol[ks] = (uint32_t)((kss * 32 + a_sel) ^ a_swx);
        bcol[ks] = (uint32_t)((kss * 32 + b_sel) ^ b_swx);
    }
    const uint32_t aRowOff = (uint32_t)((wm + a_row) * 128);
    const uint32_t bRowOff = (uint32_t)(GB_OFF + (wn + b_row) * 128);

    for (int kt = 0; kt < KT; ++kt) {
        if (kt == KT - 1) cp_wait<0>(); else cp_wait<1>();
        __syncthreads();
        if (kt + 2 < KT) load_stage((kt + 2) % 3, kt + 2);

        const uint32_t st = sbase + (kt % 3) * GSTAGE;
        const uint32_t aBase = st + aRowOff;
        const uint32_t bBase = st + bRowOff;

        #pragma unroll
        for (int ks = 0; ks < 4; ++ks) {
            unsigned a[4][4], b[8][2];
            #pragma unroll
            for (int i = 0; i < 4; ++i)
                ldsm4(a[i][0], a[i][1], a[i][2], a[i][3],
                      aBase + (uint32_t)(i * 16 * 128) + acol[ks]);
            #pragma unroll
            for (int jg = 0; jg < 4; ++jg)
                ldsm4(b[2 * jg][0], b[2 * jg + 1][0],
                      b[2 * jg][1], b[2 * jg + 1][1],
                      bBase + (uint32_t)(jg * 16 * 128) + bcol[ks]);
            #pragma unroll
            for (int i = 0; i < 4; ++i)
                #pragma unroll
                for (int j = 0; j < 8; ++j)
                    MMA_F16(acc[i][j], a[i], b[j]);
        }
    }

    // epilogue
    const float sa = fmaxf(__uint_as_float(g_amax[saslot]), 1e-8f) / 127.f;
    const float sb = fmaxf(__uint_as_float(g_amax[sbslot]), 1e-8f) / 127.f;
    const float s  = sa * sb;

    float lmax = 0.f;
    #pragma unroll
    for (int i = 0; i < 4; ++i) {
        #pragma unroll
        for (int j = 0; j < 8; ++j) {
            const int row0 = rowA0 + wm + i * 16 + (lane >> 2);
            const int col0 = colB0 + wn + j * 8 + (lane & 3) * 2;
            #pragma unroll
            for (int rr = 0; rr < 2; ++rr) {
                const int row = row0 + rr * 8;
                float t0 = fmaf(acc[i][j][rr * 2 + 0], s, bias[col0 + 0]);
                float t1 = fmaf(acc[i][j][rr * 2 + 1], s, bias[col0 + 1]);
                if (EPI == 0) {
                    t0 = 0.5f * t0 * (1.f + erff(t0 * 0.70710678118654752f));
                    t1 = 0.5f * t1 * (1.f + erff(t1 * 0.70710678118654752f));
                    lmax = fmaxf(lmax, fmaxf(fabsf(t0), fabsf(t1)));
                }
                float2 v; v.x = t0; v.y = t1;
                *(float2*)(Cout + (size_t)row * N + col0) = v;
            }
        }
    }
    if (EPI == 0) {
        #pragma unroll
        for (int o = 16; o > 0; o >>= 1)
            lmax = fmaxf(lmax, __shfl_xor_sync(0xffffffffu, lmax, o));
        if (lane == 0) atomicMax(&g_amax[3], __float_as_uint(lmax));
    }
}

#define GEMM_SMEM (3 * GSTAGE)   // 98304 B

// ---------------- launch ----------------------------------------------------
extern "C" void kernel_launch(void* const* d_in, const int* in_sizes, int n_in,
                              void* d_out, int out_size) {
    const float* x  = (const float*)d_in[0];
    const float* w1 = (const float*)d_in[1];
    const float* b1 = (const float*)d_in[2];
    const float* w2 = (const float*)d_in[3];
    const float* b2 = (const float*)d_in[4];
    float* out = (float*)d_out;

    __half *xh, *w1h, *w2h, *hh;
    float* hbuf;
    cudaGetSymbolAddress((void**)&xh,   g_xh);
    cudaGetSymbolAddress((void**)&w1h,  g_w1h);
    cudaGetSymbolAddress((void**)&w2h,  g_w2h);
    cudaGetSymbolAddress((void**)&hbuf, g_h);
    cudaGetSymbolAddress((void**)&hh,   g_hh);

    cudaFuncSetAttribute(gemm_f16_kernel<0>,
                         cudaFuncAttributeMaxDynamicSharedMemorySize, GEMM_SMEM);
    cudaFuncSetAttribute(gemm_f16_kernel<1>,
                         cudaFuncAttributeMaxDynamicSharedMemorySize, GEMM_SMEM);

    init_kernel<<<1, 32>>>();
    absmax_all_kernel<<<1536, 256>>>((const float4*)x, (const float4*)w1,
                                     (const float4*)w2);
    quant_all_kernel<<<24576, 256>>>((const float4*)x, (const float4*)w1,
                                     (const float4*)w2);
    {
        dim3 grid(H_DIM / 128, M_TOK / 128);
        gemm_f16_kernel<0><<<grid, 128, GEMM_SMEM>>>(xh, w1h, b1, hbuf,
                                                     D_DIM, H_DIM, 0, 1);
    }
    {
        int n4 = (int)(((size_t)M_TOK * H_DIM) / 4);
        quant_h_kernel<<<(n4 + 511) / 512, 256>>>((const float4*)hbuf,
                                                  (ushort4*)hh, n4);
    }
    {
        dim3 grid(D_DIM / 128, M_TOK / 128);
        gemm_f16_kernel<1><<<grid, 128, GEMM_SMEM>>>(hh, w2h, b2, out,
                                                     H_DIM, D_DIM, 3, 2);
    }
    (void)in_sizes; (void)n_in; (void)out_size;
}